// round 14
// baseline (speedup 1.0000x reference)
#include <cuda_runtime.h>
#include <cuda_fp16.h>
#include <cstdint>

// ---------------------------------------------------------------------------
// FloodGNN: 2-layer GraphSAGE + linear head, transform-then-aggregate.
// R14: gathers capped to 32 regs (__launch_bounds__(256,8) -> 8 blocks/SM,
// 100% theoretical occupancy; gather is L2-latency-bound and needs warps).
// gather<0> split into two node-halves across streams; gemm2 chunks overlap
// the opposite half's gather (tensor-bound ∥ latency-bound co-residency).
// ---------------------------------------------------------------------------

constexpr int N_NODES = 100000;
constexpr int E_EDGES = 1600000;
constexpr int IN_DIM  = 128;
constexpr int HID     = 64;
constexpr int STRIDE  = 96;
constexpr int N_HALF  = 50048;            // 391 * 128, chunk boundary

__device__ int    g_cnt[N_NODES];
__device__ int    g_csr[(size_t)N_NODES * STRIDE];
__device__ __half g_y [(size_t)N_NODES * HID];   // layer-1 messages (fp16)
__device__ float  g_z [(size_t)N_NODES * HID];   // layer-1 self (fp32)
__device__ __half g_h [(size_t)N_NODES * HID];   // layer-2 input (fp16)
__device__ __half g_y2[(size_t)N_NODES * HID];   // layer-2 messages (fp16)
__device__ float  g_z2[(size_t)N_NODES * HID];   // layer-2 self (fp32)

// ---------------------------------------------------------------------------
__global__ void k_zero_cnt() {
    int i = blockIdx.x * blockDim.x + threadIdx.x;
    if (i < N_NODES / 4)
        reinterpret_cast<int4*>(g_cnt)[i] = make_int4(0, 0, 0, 0);
}

__global__ void k_build(const int* __restrict__ ei) {
    int i = blockIdx.x * blockDim.x + threadIdx.x;
    if (i >= E_EDGES / 4) return;
    int4 s = __ldg(reinterpret_cast<const int4*>(ei) + i);
    int4 d = __ldg(reinterpret_cast<const int4*>(ei + E_EDGES) + i);
    int slot;
    slot = atomicAdd(&g_cnt[d.x], 1); if (slot < STRIDE) g_csr[(size_t)d.x * STRIDE + slot] = s.x;
    slot = atomicAdd(&g_cnt[d.y], 1); if (slot < STRIDE) g_csr[(size_t)d.y * STRIDE + slot] = s.y;
    slot = atomicAdd(&g_cnt[d.z], 1); if (slot < STRIDE) g_csr[(size_t)d.z * STRIDE + slot] = s.z;
    slot = atomicAdd(&g_cnt[d.w], 1); if (slot < STRIDE) g_csr[(size_t)d.w * STRIDE + slot] = s.w;
}

// ---------------------------------------------------------------------------
__device__ __forceinline__ uint32_t smem_u32(const void* p) {
    return (uint32_t)__cvta_generic_to_shared(p);
}
__device__ __forceinline__ void ldsm_x4(uint32_t& r0, uint32_t& r1,
                                        uint32_t& r2, uint32_t& r3, uint32_t a) {
    asm volatile("ldmatrix.sync.aligned.m8n8.x4.shared.b16 {%0,%1,%2,%3}, [%4];"
                 : "=r"(r0), "=r"(r1), "=r"(r2), "=r"(r3) : "r"(a));
}
__device__ __forceinline__ void ldsm_x4_t(uint32_t& r0, uint32_t& r1,
                                          uint32_t& r2, uint32_t& r3, uint32_t a) {
    asm volatile("ldmatrix.sync.aligned.m8n8.x4.trans.shared.b16 {%0,%1,%2,%3}, [%4];"
                 : "=r"(r0), "=r"(r1), "=r"(r2), "=r"(r3) : "r"(a));
}
__device__ __forceinline__ void mma16816(float d[4], const uint32_t a[4],
                                         uint32_t b0, uint32_t b1) {
    asm volatile(
        "mma.sync.aligned.m16n8k16.row.col.f32.f16.f16.f32 "
        "{%0,%1,%2,%3}, {%4,%5,%6,%7}, {%8,%9}, {%0,%1,%2,%3};"
        : "+f"(d[0]), "+f"(d[1]), "+f"(d[2]), "+f"(d[3])
        : "r"(a[0]), "r"(a[1]), "r"(a[2]), "r"(a[3]), "r"(b0), "r"(b1));
}

// fp16 accumulate one neighbor's 8 message cols (4 HADD2). 32-bit addressing.
__device__ __forceinline__ void accH(__half2 acc[4], int src, uint32_t poff,
                                     const __half* __restrict__ ybuf)
{
    uint4 a = __ldg(reinterpret_cast<const uint4*>(
        reinterpret_cast<const char*>(ybuf) + (((uint32_t)src << 7) + poff)));
    const __half2* ah = reinterpret_cast<const __half2*>(&a);
    acc[0] = __hadd2(acc[0], ah[0]);
    acc[1] = __hadd2(acc[1], ah[1]);
    acc[2] = __hadd2(acc[2], ah[2]);
    acc[3] = __hadd2(acc[3], ah[3]);
}

// ---------------------------------------------------------------------------
// Tensor-core transform over rows [row_base + blockIdx*128, +128):
//   yout[row] = half( feat[row] @ Wl )       (tile cols 0-63)
//   zout[row] = feat[row] @ Wr + bias (fp32) (tile cols 64-127)
// Tin = float (layer 1, K=128) or __half (layer 2, K=64, pure copy staging).
// ---------------------------------------------------------------------------
template <int K, typename Tin>
__global__ void __launch_bounds__(256, 2) k_gemm_tc(
    const Tin* __restrict__ xin,
    const float* __restrict__ Wl,
    const float* __restrict__ Wr,
    const float* __restrict__ bias,
    __half* __restrict__ yout,
    float* __restrict__ zout,
    int row_base)
{
    extern __shared__ __half sm[];
    __half* sx = sm;               // [128 rows][K]   (swizzled 8-half units)
    __half* sw = sm + 128 * K;     // [K][128 cols]   (swizzled 8-half units)

    const int tid = threadIdx.x;
    const int row0 = row_base + blockIdx.x * 128;
    constexpr int XU = K / 8;

    #pragma unroll
    for (int i = 0; i < (128 * XU) / 256; i++) {
        int t = tid + i * 256;
        int r = t / XU, u = t % XU;
        int grow = row0 + r;
        uint4 pkt;
        if constexpr (sizeof(Tin) == 4) {
            float4 f0 = make_float4(0.f, 0.f, 0.f, 0.f);
            float4 f1 = make_float4(0.f, 0.f, 0.f, 0.f);
            if (grow < N_NODES) {
                const float* p = reinterpret_cast<const float*>(xin) + (size_t)grow * K + u * 8;
                f0 = *reinterpret_cast<const float4*>(p);
                f1 = *reinterpret_cast<const float4*>(p + 4);
            }
            __half2 h[4];
            h[0] = __floats2half2_rn(f0.x, f0.y);
            h[1] = __floats2half2_rn(f0.z, f0.w);
            h[2] = __floats2half2_rn(f1.x, f1.y);
            h[3] = __floats2half2_rn(f1.z, f1.w);
            pkt = *reinterpret_cast<uint4*>(h);
        } else {
            pkt = make_uint4(0u, 0u, 0u, 0u);
            if (grow < N_NODES)
                pkt = __ldg(reinterpret_cast<const uint4*>(
                    reinterpret_cast<const __half*>(xin) + (size_t)grow * K + u * 8));
        }
        int su = u ^ (r & 7);
        *reinterpret_cast<uint4*>(&sx[r * K + su * 8]) = pkt;
    }
    #pragma unroll
    for (int i = 0; i < (K * 16) / 256; i++) {
        int t = tid + i * 256;
        int k = t >> 4, u = t & 15;
        const float* p = (u < 8) ? &Wl[k * HID + u * 8] : &Wr[k * HID + (u - 8) * 8];
        float4 f0 = *reinterpret_cast<const float4*>(p);
        float4 f1 = *reinterpret_cast<const float4*>(p + 4);
        __half2 h[4];
        h[0] = __floats2half2_rn(f0.x, f0.y);
        h[1] = __floats2half2_rn(f0.z, f0.w);
        h[2] = __floats2half2_rn(f1.x, f1.y);
        h[3] = __floats2half2_rn(f1.z, f1.w);
        int su = u ^ (k & 7);
        *reinterpret_cast<uint4*>(&sw[k * 128 + su * 8]) = *reinterpret_cast<uint4*>(h);
    }
    __syncthreads();

    const int warp = tid >> 5;
    const int lane = tid & 31;
    const int mrow = warp * 16;

    float d[16][4];
    #pragma unroll
    for (int j = 0; j < 16; j++)
        #pragma unroll
        for (int q = 0; q < 4; q++) d[j][q] = 0.f;

    const uint32_t sx_base = smem_u32(sx);
    const uint32_t sw_base = smem_u32(sw);

    #pragma unroll
    for (int k0 = 0; k0 < K; k0 += 16) {
        uint32_t a[4];
        {
            int r  = mrow + (lane & 15);
            int cu = (k0 >> 3) + (lane >> 4);
            uint32_t addr = sx_base + (uint32_t)(r * K + ((cu ^ (r & 7)) * 8)) * 2u;
            ldsm_x4(a[0], a[1], a[2], a[3], addr);
        }
        #pragma unroll
        for (int nc = 0; nc < 8; nc++) {
            int k  = k0 + (lane & 15);
            int bu = nc * 2 + (lane >> 4);
            uint32_t addr = sw_base + (uint32_t)(k * 128 + ((bu ^ (k & 7)) * 8)) * 2u;
            uint32_t b0, b1, b2, b3;
            ldsm_x4_t(b0, b1, b2, b3, addr);
            mma16816(d[nc * 2],     a, b0, b1);
            mma16816(d[nc * 2 + 1], a, b2, b3);
        }
    }

    const int g   = lane >> 2;
    const int tig = lane & 3;
    const int ra  = row0 + mrow + g;
    const int rb  = ra + 8;
    #pragma unroll
    for (int jj = 0; jj < 16; jj++) {
        int c = jj * 8 + tig * 2;
        if (c < HID) {
            __half2 va = __floats2half2_rn(d[jj][0], d[jj][1]);
            __half2 vb = __floats2half2_rn(d[jj][2], d[jj][3]);
            if (ra < N_NODES) *reinterpret_cast<__half2*>(&yout[(size_t)ra * HID + c]) = va;
            if (rb < N_NODES) *reinterpret_cast<__half2*>(&yout[(size_t)rb * HID + c]) = vb;
        } else {
            int cz = c - HID;
            float bx = __ldg(&bias[cz]);
            float by = __ldg(&bias[cz + 1]);
            if (ra < N_NODES)
                *reinterpret_cast<float2*>(&zout[(size_t)ra * HID + cz]) =
                    make_float2(d[jj][0] + bx, d[jj][1] + by);
            if (rb < N_NODES)
                *reinterpret_cast<float2*>(&zout[(size_t)rb * HID + cz]) =
                    make_float2(d[jj][2] + bx, d[jj][3] + by);
        }
    }
}

constexpr int SMEM_TC1 = 2 * 128 * IN_DIM * (int)sizeof(__half);  // 64 KB
constexpr int SMEM_TC2 = 2 * 128 * HID * (int)sizeof(__half);     // 32 KB

// ---------------------------------------------------------------------------
// CSR gather over dsts [base, limit): 8 threads per dst row; thread owns
// 8 fp16 message cols. fp16 accumulation (2 interleaved sets), fp32 finish.
//   FINAL=false: g_h[dst] = half(h)       FINAL=true: out[dst] = h@Wc + bc
// 32-reg cap (minBlocks=8): gather is latency-bound; occupancy is the lever.
// ---------------------------------------------------------------------------
template <bool FINAL>
__global__ void __launch_bounds__(256, 8) k_gather(
    const __half* __restrict__ ybuf,
    const float* __restrict__ zbuf,
    const float* __restrict__ Wc,
    const float* __restrict__ bc,
    float* __restrict__ out,
    int base, int limit)
{
    int t = blockIdx.x * blockDim.x + threadIdx.x;
    int dst = base + (t >> 3);
    int part = t & 7;
    if (dst >= limit) return;
    uint32_t poff = (uint32_t)part << 4;   // byte offset of this 16B slice

    int deg = g_cnt[dst];
    int n = deg < STRIDE ? deg : STRIDE;
    const int* lst = &g_csr[(size_t)dst * STRIDE];

    __half2 zero2 = __float2half2_rn(0.f);
    __half2 aA[4] = {zero2, zero2, zero2, zero2};
    __half2 aB[4] = {zero2, zero2, zero2, zero2};

    int j = 0;
    for (; j + 4 <= n; j += 4) {
        int4 i0 = __ldg(reinterpret_cast<const int4*>(lst + j));
        accH(aA, i0.x, poff, ybuf);
        accH(aB, i0.y, poff, ybuf);
        accH(aA, i0.z, poff, ybuf);
        accH(aB, i0.w, poff, ybuf);
    }
    for (; j < n; j++)
        accH(aA, __ldg(&lst[j]), poff, ybuf);

    // fp32 finish
    float2 s0 = __half22float2(aA[0]); float2 t0 = __half22float2(aB[0]);
    float2 s1 = __half22float2(aA[1]); float2 t1 = __half22float2(aB[1]);
    float2 s2 = __half22float2(aA[2]); float2 t2 = __half22float2(aB[2]);
    float2 s3 = __half22float2(aA[3]); float2 t3 = __half22float2(aB[3]);

    float inv = 1.0f / fmaxf((float)deg, 1.0f);
    size_t zb = (size_t)dst * HID + part * 8;
    float4 z0 = *reinterpret_cast<const float4*>(&zbuf[zb]);
    float4 z1 = *reinterpret_cast<const float4*>(&zbuf[zb + 4]);

    float h0 = fmaxf(fmaf(s0.x + t0.x, inv, z0.x), 0.f);
    float h1 = fmaxf(fmaf(s0.y + t0.y, inv, z0.y), 0.f);
    float h2 = fmaxf(fmaf(s1.x + t1.x, inv, z0.z), 0.f);
    float h3 = fmaxf(fmaf(s1.y + t1.y, inv, z0.w), 0.f);
    float h4 = fmaxf(fmaf(s2.x + t2.x, inv, z1.x), 0.f);
    float h5 = fmaxf(fmaf(s2.y + t2.y, inv, z1.y), 0.f);
    float h6 = fmaxf(fmaf(s3.x + t3.x, inv, z1.z), 0.f);
    float h7 = fmaxf(fmaf(s3.y + t3.y, inv, z1.w), 0.f);

    if (!FINAL) {
        __half2 hp[4];
        hp[0] = __floats2half2_rn(h0, h1);
        hp[1] = __floats2half2_rn(h2, h3);
        hp[2] = __floats2half2_rn(h4, h5);
        hp[3] = __floats2half2_rn(h6, h7);
        *reinterpret_cast<uint4*>(&g_h[(size_t)dst * HID + part * 8]) =
            *reinterpret_cast<uint4*>(hp);
    } else {
        float4 w0 = *reinterpret_cast<const float4*>(&Wc[part * 8]);
        float4 w1 = *reinterpret_cast<const float4*>(&Wc[part * 8 + 4]);
        float s = h0 * w0.x + h1 * w0.y + h2 * w0.z + h3 * w0.w
                + h4 * w1.x + h5 * w1.y + h6 * w1.z + h7 * w1.w;
        #pragma unroll
        for (int o = 4; o > 0; o >>= 1)
            s += __shfl_down_sync(0xffffffffu, s, o, 8);
        if (part == 0) out[dst] = s + __ldg(&bc[0]);
    }
}

// ---------------------------------------------------------------------------
extern "C" void kernel_launch(void* const* d_in, const int* in_sizes, int n_in,
                              void* d_out, int out_size)
{
    const float* x   = (const float*)d_in[0];
    const int*   ei  = (const int*)  d_in[1];
    const float* W1l = (const float*)d_in[2];
    const float* W1r = (const float*)d_in[3];
    const float* b1  = (const float*)d_in[4];
    const float* W2l = (const float*)d_in[5];
    const float* W2r = (const float*)d_in[6];
    const float* b2  = (const float*)d_in[7];
    const float* Wc  = (const float*)d_in[8];
    const float* bc  = (const float*)d_in[9];
    float* out = (float*)d_out;

    void *py = nullptr, *pz = nullptr, *ph = nullptr, *py2 = nullptr, *pz2 = nullptr;
    cudaGetSymbolAddress(&py,  g_y);
    cudaGetSymbolAddress(&pz,  g_z);
    cudaGetSymbolAddress(&ph,  g_h);
    cudaGetSymbolAddress(&py2, g_y2);
    cudaGetSymbolAddress(&pz2, g_z2);

    cudaFuncSetAttribute((const void*)&k_gemm_tc<IN_DIM, float>,
                         cudaFuncAttributeMaxDynamicSharedMemorySize, SMEM_TC1);
    cudaFuncSetAttribute((const void*)&k_gemm_tc<HID, __half>,
                         cudaFuncAttributeMaxDynamicSharedMemorySize, SMEM_TC2);

    constexpr int ZC_BLKS    = (N_NODES / 4 + 255) / 256;                 // 98
    constexpr int BUILD_BLKS = (E_EDGES / 4 + 255) / 256;                 // 1563
    constexpr int GEMM1_BLKS = (N_NODES + 127) / 128;                     // 782
    constexpr int GEMM2A     = N_HALF / 128;                              // 391
    constexpr int GEMM2B     = (N_NODES - N_HALF + 127) / 128;            // 391
    constexpr int GA_BLKS    = (N_HALF * 8 + 255) / 256;                  // 1564
    constexpr int GB_BLKS    = ((N_NODES - N_HALF) * 8 + 255) / 256;      // 1561
    constexpr int GF_BLKS    = (N_NODES * 8 + 255) / 256;                 // 3125

    cudaStream_t s2;
    cudaEvent_t evFork, evJoin, evG1, evB;
    cudaStreamCreateWithFlags(&s2, cudaStreamNonBlocking);
    cudaEventCreateWithFlags(&evFork, cudaEventDisableTiming);
    cudaEventCreateWithFlags(&evJoin, cudaEventDisableTiming);
    cudaEventCreateWithFlags(&evG1,   cudaEventDisableTiming);
    cudaEventCreateWithFlags(&evB,    cudaEventDisableTiming);

    // Fork: [zero_cnt -> build] on s2, overlapping gemm1 on main.
    cudaEventRecord(evFork, 0);
    cudaStreamWaitEvent(s2, evFork, 0);
    k_zero_cnt<<<ZC_BLKS, 256, 0, s2>>>();
    k_build<<<BUILD_BLKS, 256, 0, s2>>>(ei);
    cudaEventRecord(evJoin, s2);

    k_gemm_tc<IN_DIM, float><<<GEMM1_BLKS, 256, SMEM_TC1>>>(
        x, W1l, W1r, b1, (__half*)py, (float*)pz, 0);

    cudaStreamWaitEvent(0, evJoin, 0);    // main now has gemm1 + build done
    cudaEventRecord(evG1, 0);
    cudaStreamWaitEvent(s2, evG1, 0);

    // gather<0> split: half A on main, half B on s2 (concurrent).
    k_gather<false><<<GA_BLKS, 256>>>((const __half*)py, (const float*)pz,
                                      nullptr, nullptr, nullptr, 0, N_HALF);
    k_gather<false><<<GB_BLKS, 256, 0, s2>>>((const __half*)py, (const float*)pz,
                                             nullptr, nullptr, nullptr,
                                             N_HALF, N_NODES);
    cudaEventRecord(evB, s2);

    // gemm2(A) overlaps tail of gather<0>(B); gemm2(B) after its half lands.
    k_gemm_tc<HID, __half><<<GEMM2A, 256, SMEM_TC2>>>(
        (const __half*)ph, W2l, W2r, b2, (__half*)py2, (float*)pz2, 0);
    cudaStreamWaitEvent(0, evB, 0);
    k_gemm_tc<HID, __half><<<GEMM2B, 256, SMEM_TC2>>>(
        (const __half*)ph, W2l, W2r, b2, (__half*)py2, (float*)pz2, N_HALF);

    k_gather<true><<<GF_BLKS, 256>>>((const __half*)py2, (const float*)pz2,
                                     Wc, bc, out, 0, N_NODES);

    cudaEventDestroy(evFork);
    cudaEventDestroy(evJoin);
    cudaEventDestroy(evG1);
    cudaEventDestroy(evB);
    cudaStreamDestroy(s2);
}

// round 15
// speedup vs baseline: 1.0096x; 1.0096x over previous
#include <cuda_runtime.h>
#include <cuda_fp16.h>
#include <cstdint>

// ---------------------------------------------------------------------------
// FloodGNN: 2-layer GraphSAGE + linear head, transform-then-aggregate.
// R15: revert R14's reg-cap/split (per-work slowdown: MLP is register-funded).
// R13 skeleton; gathers now 16 threads/row with 8B uint2 loads -> 2x warps,
// half-length chains, ~30 regs naturally. Dense layers on tensor cores.
// ---------------------------------------------------------------------------

constexpr int N_NODES = 100000;
constexpr int E_EDGES = 1600000;
constexpr int IN_DIM  = 128;
constexpr int HID     = 64;
constexpr int STRIDE  = 96;

__device__ int    g_cnt[N_NODES];
__device__ int    g_csr[(size_t)N_NODES * STRIDE];
__device__ __half g_y [(size_t)N_NODES * HID];   // layer-1 messages (fp16)
__device__ float  g_z [(size_t)N_NODES * HID];   // layer-1 self (fp32)
__device__ __half g_h [(size_t)N_NODES * HID];   // layer-2 input (fp16)
__device__ __half g_y2[(size_t)N_NODES * HID];   // layer-2 messages (fp16)
__device__ float  g_z2[(size_t)N_NODES * HID];   // layer-2 self (fp32)

// ---------------------------------------------------------------------------
__global__ void k_zero_cnt() {
    int i = blockIdx.x * blockDim.x + threadIdx.x;
    if (i < N_NODES / 4)
        reinterpret_cast<int4*>(g_cnt)[i] = make_int4(0, 0, 0, 0);
}

__global__ void k_build(const int* __restrict__ ei) {
    int i = blockIdx.x * blockDim.x + threadIdx.x;
    if (i >= E_EDGES / 4) return;
    int4 s = __ldg(reinterpret_cast<const int4*>(ei) + i);
    int4 d = __ldg(reinterpret_cast<const int4*>(ei + E_EDGES) + i);
    int slot;
    slot = atomicAdd(&g_cnt[d.x], 1); if (slot < STRIDE) g_csr[(size_t)d.x * STRIDE + slot] = s.x;
    slot = atomicAdd(&g_cnt[d.y], 1); if (slot < STRIDE) g_csr[(size_t)d.y * STRIDE + slot] = s.y;
    slot = atomicAdd(&g_cnt[d.z], 1); if (slot < STRIDE) g_csr[(size_t)d.z * STRIDE + slot] = s.z;
    slot = atomicAdd(&g_cnt[d.w], 1); if (slot < STRIDE) g_csr[(size_t)d.w * STRIDE + slot] = s.w;
}

// ---------------------------------------------------------------------------
__device__ __forceinline__ uint32_t smem_u32(const void* p) {
    return (uint32_t)__cvta_generic_to_shared(p);
}
__device__ __forceinline__ void ldsm_x4(uint32_t& r0, uint32_t& r1,
                                        uint32_t& r2, uint32_t& r3, uint32_t a) {
    asm volatile("ldmatrix.sync.aligned.m8n8.x4.shared.b16 {%0,%1,%2,%3}, [%4];"
                 : "=r"(r0), "=r"(r1), "=r"(r2), "=r"(r3) : "r"(a));
}
__device__ __forceinline__ void ldsm_x4_t(uint32_t& r0, uint32_t& r1,
                                          uint32_t& r2, uint32_t& r3, uint32_t a) {
    asm volatile("ldmatrix.sync.aligned.m8n8.x4.trans.shared.b16 {%0,%1,%2,%3}, [%4];"
                 : "=r"(r0), "=r"(r1), "=r"(r2), "=r"(r3) : "r"(a));
}
__device__ __forceinline__ void mma16816(float d[4], const uint32_t a[4],
                                         uint32_t b0, uint32_t b1) {
    asm volatile(
        "mma.sync.aligned.m16n8k16.row.col.f32.f16.f16.f32 "
        "{%0,%1,%2,%3}, {%4,%5,%6,%7}, {%8,%9}, {%0,%1,%2,%3};"
        : "+f"(d[0]), "+f"(d[1]), "+f"(d[2]), "+f"(d[3])
        : "r"(a[0]), "r"(a[1]), "r"(a[2]), "r"(a[3]), "r"(b0), "r"(b1));
}

// fp16 accumulate one neighbor's 4 message cols (2 HADD2, 8B load).
__device__ __forceinline__ void accH2(__half2 acc[2], int src, uint32_t poff,
                                      const __half* __restrict__ ybuf)
{
    uint2 a = __ldg(reinterpret_cast<const uint2*>(
        reinterpret_cast<const char*>(ybuf) + (((uint32_t)src << 7) + poff)));
    const __half2* ah = reinterpret_cast<const __half2*>(&a);
    acc[0] = __hadd2(acc[0], ah[0]);
    acc[1] = __hadd2(acc[1], ah[1]);
}

// ---------------------------------------------------------------------------
// Tensor-core transform. Per 128-row block:
//   yout[row] = half( feat[row] @ Wl )       (tile cols 0-63)
//   zout[row] = feat[row] @ Wr + bias (fp32) (tile cols 64-127)
// Tin = float (layer 1, K=128) or __half (layer 2, K=64, pure copy staging).
// ---------------------------------------------------------------------------
template <int K, typename Tin>
__global__ void __launch_bounds__(256, 2) k_gemm_tc(
    const Tin* __restrict__ xin,
    const float* __restrict__ Wl,
    const float* __restrict__ Wr,
    const float* __restrict__ bias,
    __half* __restrict__ yout,
    float* __restrict__ zout)
{
    extern __shared__ __half sm[];
    __half* sx = sm;               // [128 rows][K]   (swizzled 8-half units)
    __half* sw = sm + 128 * K;     // [K][128 cols]   (swizzled 8-half units)

    const int tid = threadIdx.x;
    const int row0 = blockIdx.x * 128;
    constexpr int XU = K / 8;

    #pragma unroll
    for (int i = 0; i < (128 * XU) / 256; i++) {
        int t = tid + i * 256;
        int r = t / XU, u = t % XU;
        int grow = row0 + r;
        uint4 pkt;
        if constexpr (sizeof(Tin) == 4) {
            float4 f0 = make_float4(0.f, 0.f, 0.f, 0.f);
            float4 f1 = make_float4(0.f, 0.f, 0.f, 0.f);
            if (grow < N_NODES) {
                const float* p = reinterpret_cast<const float*>(xin) + (size_t)grow * K + u * 8;
                f0 = *reinterpret_cast<const float4*>(p);
                f1 = *reinterpret_cast<const float4*>(p + 4);
            }
            __half2 h[4];
            h[0] = __floats2half2_rn(f0.x, f0.y);
            h[1] = __floats2half2_rn(f0.z, f0.w);
            h[2] = __floats2half2_rn(f1.x, f1.y);
            h[3] = __floats2half2_rn(f1.z, f1.w);
            pkt = *reinterpret_cast<uint4*>(h);
        } else {
            pkt = make_uint4(0u, 0u, 0u, 0u);
            if (grow < N_NODES)
                pkt = __ldg(reinterpret_cast<const uint4*>(
                    reinterpret_cast<const __half*>(xin) + (size_t)grow * K + u * 8));
        }
        int su = u ^ (r & 7);
        *reinterpret_cast<uint4*>(&sx[r * K + su * 8]) = pkt;
    }
    #pragma unroll
    for (int i = 0; i < (K * 16) / 256; i++) {
        int t = tid + i * 256;
        int k = t >> 4, u = t & 15;
        const float* p = (u < 8) ? &Wl[k * HID + u * 8] : &Wr[k * HID + (u - 8) * 8];
        float4 f0 = *reinterpret_cast<const float4*>(p);
        float4 f1 = *reinterpret_cast<const float4*>(p + 4);
        __half2 h[4];
        h[0] = __floats2half2_rn(f0.x, f0.y);
        h[1] = __floats2half2_rn(f0.z, f0.w);
        h[2] = __floats2half2_rn(f1.x, f1.y);
        h[3] = __floats2half2_rn(f1.z, f1.w);
        int su = u ^ (k & 7);
        *reinterpret_cast<uint4*>(&sw[k * 128 + su * 8]) = *reinterpret_cast<uint4*>(h);
    }
    __syncthreads();

    const int warp = tid >> 5;
    const int lane = tid & 31;
    const int mrow = warp * 16;

    float d[16][4];
    #pragma unroll
    for (int j = 0; j < 16; j++)
        #pragma unroll
        for (int q = 0; q < 4; q++) d[j][q] = 0.f;

    const uint32_t sx_base = smem_u32(sx);
    const uint32_t sw_base = smem_u32(sw);

    #pragma unroll
    for (int k0 = 0; k0 < K; k0 += 16) {
        uint32_t a[4];
        {
            int r  = mrow + (lane & 15);
            int cu = (k0 >> 3) + (lane >> 4);
            uint32_t addr = sx_base + (uint32_t)(r * K + ((cu ^ (r & 7)) * 8)) * 2u;
            ldsm_x4(a[0], a[1], a[2], a[3], addr);
        }
        #pragma unroll
        for (int nc = 0; nc < 8; nc++) {
            int k  = k0 + (lane & 15);
            int bu = nc * 2 + (lane >> 4);
            uint32_t addr = sw_base + (uint32_t)(k * 128 + ((bu ^ (k & 7)) * 8)) * 2u;
            uint32_t b0, b1, b2, b3;
            ldsm_x4_t(b0, b1, b2, b3, addr);
            mma16816(d[nc * 2],     a, b0, b1);
            mma16816(d[nc * 2 + 1], a, b2, b3);
        }
    }

    const int g   = lane >> 2;
    const int tig = lane & 3;
    const int ra  = row0 + mrow + g;
    const int rb  = ra + 8;
    #pragma unroll
    for (int jj = 0; jj < 16; jj++) {
        int c = jj * 8 + tig * 2;
        if (c < HID) {
            __half2 va = __floats2half2_rn(d[jj][0], d[jj][1]);
            __half2 vb = __floats2half2_rn(d[jj][2], d[jj][3]);
            if (ra < N_NODES) *reinterpret_cast<__half2*>(&yout[(size_t)ra * HID + c]) = va;
            if (rb < N_NODES) *reinterpret_cast<__half2*>(&yout[(size_t)rb * HID + c]) = vb;
        } else {
            int cz = c - HID;
            float bx = __ldg(&bias[cz]);
            float by = __ldg(&bias[cz + 1]);
            if (ra < N_NODES)
                *reinterpret_cast<float2*>(&zout[(size_t)ra * HID + cz]) =
                    make_float2(d[jj][0] + bx, d[jj][1] + by);
            if (rb < N_NODES)
                *reinterpret_cast<float2*>(&zout[(size_t)rb * HID + cz]) =
                    make_float2(d[jj][2] + bx, d[jj][3] + by);
        }
    }
}

constexpr int SMEM_TC1 = 2 * 128 * IN_DIM * (int)sizeof(__half);  // 64 KB
constexpr int SMEM_TC2 = 2 * 128 * HID * (int)sizeof(__half);     // 32 KB

// ---------------------------------------------------------------------------
// CSR gather: 16 threads per dst row; thread owns 4 fp16 message cols
// (one 8B uint2 load per neighbor). fp16 accumulation, 2 interleaved sets,
// fp32 finish: h = relu((sumA+sumB)*inv + z).
//   FINAL=false: g_h[dst] = half(h)       FINAL=true: out[dst] = h@Wc + bc
// No launch-bounds cap: in-flight loads are register-funded (R14 lesson).
// ---------------------------------------------------------------------------
template <bool FINAL>
__global__ void __launch_bounds__(256) k_gather(
    const __half* __restrict__ ybuf,
    const float* __restrict__ zbuf,
    const float* __restrict__ Wc,
    const float* __restrict__ bc,
    float* __restrict__ out)
{
    int t = blockIdx.x * blockDim.x + threadIdx.x;
    int dst = t >> 4;
    int part = t & 15;
    if (dst >= N_NODES) return;
    uint32_t poff = (uint32_t)part << 3;   // byte offset of this 8B slice

    int deg = g_cnt[dst];
    int n = deg < STRIDE ? deg : STRIDE;
    const int* lst = &g_csr[(size_t)dst * STRIDE];

    __half2 zero2 = __float2half2_rn(0.f);
    __half2 aA[2] = {zero2, zero2};
    __half2 aB[2] = {zero2, zero2};

    int j = 0;
    for (; j + 4 <= n; j += 4) {
        int4 i0 = __ldg(reinterpret_cast<const int4*>(lst + j));
        accH2(aA, i0.x, poff, ybuf);
        accH2(aB, i0.y, poff, ybuf);
        accH2(aA, i0.z, poff, ybuf);
        accH2(aB, i0.w, poff, ybuf);
    }
    for (; j < n; j++)
        accH2(aA, __ldg(&lst[j]), poff, ybuf);

    // fp32 finish
    float2 s0 = __half22float2(aA[0]); float2 t0 = __half22float2(aB[0]);
    float2 s1 = __half22float2(aA[1]); float2 t1 = __half22float2(aB[1]);

    float inv = 1.0f / fmaxf((float)deg, 1.0f);
    float4 zv = *reinterpret_cast<const float4*>(&zbuf[(size_t)dst * HID + part * 4]);

    float h0 = fmaxf(fmaf(s0.x + t0.x, inv, zv.x), 0.f);
    float h1 = fmaxf(fmaf(s0.y + t0.y, inv, zv.y), 0.f);
    float h2 = fmaxf(fmaf(s1.x + t1.x, inv, zv.z), 0.f);
    float h3 = fmaxf(fmaf(s1.y + t1.y, inv, zv.w), 0.f);

    if (!FINAL) {
        __half2 hp[2];
        hp[0] = __floats2half2_rn(h0, h1);
        hp[1] = __floats2half2_rn(h2, h3);
        *reinterpret_cast<uint2*>(&g_h[(size_t)dst * HID + part * 4]) =
            *reinterpret_cast<uint2*>(hp);
    } else {
        float4 wc = *reinterpret_cast<const float4*>(&Wc[part * 4]);
        float s = h0 * wc.x + h1 * wc.y + h2 * wc.z + h3 * wc.w;
        #pragma unroll
        for (int o = 8; o > 0; o >>= 1)
            s += __shfl_down_sync(0xffffffffu, s, o, 16);
        if (part == 0) out[dst] = s + __ldg(&bc[0]);
    }
}

// ---------------------------------------------------------------------------
extern "C" void kernel_launch(void* const* d_in, const int* in_sizes, int n_in,
                              void* d_out, int out_size)
{
    const float* x   = (const float*)d_in[0];
    const int*   ei  = (const int*)  d_in[1];
    const float* W1l = (const float*)d_in[2];
    const float* W1r = (const float*)d_in[3];
    const float* b1  = (const float*)d_in[4];
    const float* W2l = (const float*)d_in[5];
    const float* W2r = (const float*)d_in[6];
    const float* b2  = (const float*)d_in[7];
    const float* Wc  = (const float*)d_in[8];
    const float* bc  = (const float*)d_in[9];
    float* out = (float*)d_out;

    void *py = nullptr, *pz = nullptr, *ph = nullptr, *py2 = nullptr, *pz2 = nullptr;
    cudaGetSymbolAddress(&py,  g_y);
    cudaGetSymbolAddress(&pz,  g_z);
    cudaGetSymbolAddress(&ph,  g_h);
    cudaGetSymbolAddress(&py2, g_y2);
    cudaGetSymbolAddress(&pz2, g_z2);

    cudaFuncSetAttribute((const void*)&k_gemm_tc<IN_DIM, float>,
                         cudaFuncAttributeMaxDynamicSharedMemorySize, SMEM_TC1);
    cudaFuncSetAttribute((const void*)&k_gemm_tc<HID, __half>,
                         cudaFuncAttributeMaxDynamicSharedMemorySize, SMEM_TC2);

    constexpr int ZC_BLKS    = (N_NODES / 4 + 255) / 256;                 // 98
    constexpr int BUILD_BLKS = (E_EDGES / 4 + 255) / 256;                 // 1563
    constexpr int GEMM_BLKS  = (N_NODES + 127) / 128;                     // 782
    constexpr int GATH_BLKS  = (int)(((size_t)N_NODES * 16 + 255) / 256); // 6250

    // Fork: [zero_cnt -> build] overlaps gemm1 (independent pipes).
    cudaStream_t s2;
    cudaEvent_t evFork, evJoin;
    cudaStreamCreateWithFlags(&s2, cudaStreamNonBlocking);
    cudaEventCreateWithFlags(&evFork, cudaEventDisableTiming);
    cudaEventCreateWithFlags(&evJoin, cudaEventDisableTiming);

    cudaEventRecord(evFork, 0);
    cudaStreamWaitEvent(s2, evFork, 0);
    k_zero_cnt<<<ZC_BLKS, 256, 0, s2>>>();
    k_build<<<BUILD_BLKS, 256, 0, s2>>>(ei);
    cudaEventRecord(evJoin, s2);

    k_gemm_tc<IN_DIM, float><<<GEMM_BLKS, 256, SMEM_TC1>>>(
        x, W1l, W1r, b1, (__half*)py, (float*)pz);

    cudaStreamWaitEvent(0, evJoin, 0);
    k_gather<false><<<GATH_BLKS, 256>>>((const __half*)py, (const float*)pz,
                                        nullptr, nullptr, nullptr);
    k_gemm_tc<HID, __half><<<GEMM_BLKS, 256, SMEM_TC2>>>(
        (const __half*)ph, W2l, W2r, b2, (__half*)py2, (float*)pz2);
    k_gather<true><<<GATH_BLKS, 256>>>((const __half*)py2, (const float*)pz2,
                                       Wc, bc, out);

    cudaEventDestroy(evFork);
    cudaEventDestroy(evJoin);
    cudaStreamDestroy(s2);
}

// round 16
// speedup vs baseline: 1.0499x; 1.0399x over previous
#include <cuda_runtime.h>
#include <cuda_fp16.h>
#include <cstdint>

// ---------------------------------------------------------------------------
// FloodGNN: 2-layer GraphSAGE + linear head, transform-then-aggregate.
// R16: R13 base (8 thr/row, 16B loads, fp16 accum — best stable gather) with
// software-pipelined index prefetch: next int4 index quad is loaded while the
// current quad's features are accumulated, hiding the index L2 latency.
// Dense layers on tensor cores; stream-fork build; fused head.
// ---------------------------------------------------------------------------

constexpr int N_NODES = 100000;
constexpr int E_EDGES = 1600000;
constexpr int IN_DIM  = 128;
constexpr int HID     = 64;
constexpr int STRIDE  = 96;

__device__ int    g_cnt[N_NODES];
__device__ int    g_csr[(size_t)N_NODES * STRIDE];
__device__ __half g_y [(size_t)N_NODES * HID];   // layer-1 messages (fp16)
__device__ float  g_z [(size_t)N_NODES * HID];   // layer-1 self (fp32)
__device__ __half g_h [(size_t)N_NODES * HID];   // layer-2 input (fp16)
__device__ __half g_y2[(size_t)N_NODES * HID];   // layer-2 messages (fp16)
__device__ float  g_z2[(size_t)N_NODES * HID];   // layer-2 self (fp32)

// ---------------------------------------------------------------------------
__global__ void k_zero_cnt() {
    int i = blockIdx.x * blockDim.x + threadIdx.x;
    if (i < N_NODES / 4)
        reinterpret_cast<int4*>(g_cnt)[i] = make_int4(0, 0, 0, 0);
}

__global__ void k_build(const int* __restrict__ ei) {
    int i = blockIdx.x * blockDim.x + threadIdx.x;
    if (i >= E_EDGES / 4) return;
    int4 s = __ldg(reinterpret_cast<const int4*>(ei) + i);
    int4 d = __ldg(reinterpret_cast<const int4*>(ei + E_EDGES) + i);
    int slot;
    slot = atomicAdd(&g_cnt[d.x], 1); if (slot < STRIDE) g_csr[(size_t)d.x * STRIDE + slot] = s.x;
    slot = atomicAdd(&g_cnt[d.y], 1); if (slot < STRIDE) g_csr[(size_t)d.y * STRIDE + slot] = s.y;
    slot = atomicAdd(&g_cnt[d.z], 1); if (slot < STRIDE) g_csr[(size_t)d.z * STRIDE + slot] = s.z;
    slot = atomicAdd(&g_cnt[d.w], 1); if (slot < STRIDE) g_csr[(size_t)d.w * STRIDE + slot] = s.w;
}

// ---------------------------------------------------------------------------
__device__ __forceinline__ uint32_t smem_u32(const void* p) {
    return (uint32_t)__cvta_generic_to_shared(p);
}
__device__ __forceinline__ void ldsm_x4(uint32_t& r0, uint32_t& r1,
                                        uint32_t& r2, uint32_t& r3, uint32_t a) {
    asm volatile("ldmatrix.sync.aligned.m8n8.x4.shared.b16 {%0,%1,%2,%3}, [%4];"
                 : "=r"(r0), "=r"(r1), "=r"(r2), "=r"(r3) : "r"(a));
}
__device__ __forceinline__ void ldsm_x4_t(uint32_t& r0, uint32_t& r1,
                                          uint32_t& r2, uint32_t& r3, uint32_t a) {
    asm volatile("ldmatrix.sync.aligned.m8n8.x4.trans.shared.b16 {%0,%1,%2,%3}, [%4];"
                 : "=r"(r0), "=r"(r1), "=r"(r2), "=r"(r3) : "r"(a));
}
__device__ __forceinline__ void mma16816(float d[4], const uint32_t a[4],
                                         uint32_t b0, uint32_t b1) {
    asm volatile(
        "mma.sync.aligned.m16n8k16.row.col.f32.f16.f16.f32 "
        "{%0,%1,%2,%3}, {%4,%5,%6,%7}, {%8,%9}, {%0,%1,%2,%3};"
        : "+f"(d[0]), "+f"(d[1]), "+f"(d[2]), "+f"(d[3])
        : "r"(a[0]), "r"(a[1]), "r"(a[2]), "r"(a[3]), "r"(b0), "r"(b1));
}

// fp16 accumulate one neighbor's 8 message cols (4 HADD2, 16B load).
__device__ __forceinline__ void accH(__half2 acc[4], int src, uint32_t poff,
                                     const __half* __restrict__ ybuf)
{
    uint4 a = __ldg(reinterpret_cast<const uint4*>(
        reinterpret_cast<const char*>(ybuf) + (((uint32_t)src << 7) + poff)));
    const __half2* ah = reinterpret_cast<const __half2*>(&a);
    acc[0] = __hadd2(acc[0], ah[0]);
    acc[1] = __hadd2(acc[1], ah[1]);
    acc[2] = __hadd2(acc[2], ah[2]);
    acc[3] = __hadd2(acc[3], ah[3]);
}

// ---------------------------------------------------------------------------
// Tensor-core transform. Per 128-row block:
//   yout[row] = half( feat[row] @ Wl )       (tile cols 0-63)
//   zout[row] = feat[row] @ Wr + bias (fp32) (tile cols 64-127)
// Tin = float (layer 1, K=128) or __half (layer 2, K=64, pure copy staging).
// ---------------------------------------------------------------------------
template <int K, typename Tin>
__global__ void __launch_bounds__(256, 2) k_gemm_tc(
    const Tin* __restrict__ xin,
    const float* __restrict__ Wl,
    const float* __restrict__ Wr,
    const float* __restrict__ bias,
    __half* __restrict__ yout,
    float* __restrict__ zout)
{
    extern __shared__ __half sm[];
    __half* sx = sm;               // [128 rows][K]   (swizzled 8-half units)
    __half* sw = sm + 128 * K;     // [K][128 cols]   (swizzled 8-half units)

    const int tid = threadIdx.x;
    const int row0 = blockIdx.x * 128;
    constexpr int XU = K / 8;

    #pragma unroll
    for (int i = 0; i < (128 * XU) / 256; i++) {
        int t = tid + i * 256;
        int r = t / XU, u = t % XU;
        int grow = row0 + r;
        uint4 pkt;
        if constexpr (sizeof(Tin) == 4) {
            float4 f0 = make_float4(0.f, 0.f, 0.f, 0.f);
            float4 f1 = make_float4(0.f, 0.f, 0.f, 0.f);
            if (grow < N_NODES) {
                const float* p = reinterpret_cast<const float*>(xin) + (size_t)grow * K + u * 8;
                f0 = *reinterpret_cast<const float4*>(p);
                f1 = *reinterpret_cast<const float4*>(p + 4);
            }
            __half2 h[4];
            h[0] = __floats2half2_rn(f0.x, f0.y);
            h[1] = __floats2half2_rn(f0.z, f0.w);
            h[2] = __floats2half2_rn(f1.x, f1.y);
            h[3] = __floats2half2_rn(f1.z, f1.w);
            pkt = *reinterpret_cast<uint4*>(h);
        } else {
            pkt = make_uint4(0u, 0u, 0u, 0u);
            if (grow < N_NODES)
                pkt = __ldg(reinterpret_cast<const uint4*>(
                    reinterpret_cast<const __half*>(xin) + (size_t)grow * K + u * 8));
        }
        int su = u ^ (r & 7);
        *reinterpret_cast<uint4*>(&sx[r * K + su * 8]) = pkt;
    }
    #pragma unroll
    for (int i = 0; i < (K * 16) / 256; i++) {
        int t = tid + i * 256;
        int k = t >> 4, u = t & 15;
        const float* p = (u < 8) ? &Wl[k * HID + u * 8] : &Wr[k * HID + (u - 8) * 8];
        float4 f0 = *reinterpret_cast<const float4*>(p);
        float4 f1 = *reinterpret_cast<const float4*>(p + 4);
        __half2 h[4];
        h[0] = __floats2half2_rn(f0.x, f0.y);
        h[1] = __floats2half2_rn(f0.z, f0.w);
        h[2] = __floats2half2_rn(f1.x, f1.y);
        h[3] = __floats2half2_rn(f1.z, f1.w);
        int su = u ^ (k & 7);
        *reinterpret_cast<uint4*>(&sw[k * 128 + su * 8]) = *reinterpret_cast<uint4*>(h);
    }
    __syncthreads();

    const int warp = tid >> 5;
    const int lane = tid & 31;
    const int mrow = warp * 16;

    float d[16][4];
    #pragma unroll
    for (int j = 0; j < 16; j++)
        #pragma unroll
        for (int q = 0; q < 4; q++) d[j][q] = 0.f;

    const uint32_t sx_base = smem_u32(sx);
    const uint32_t sw_base = smem_u32(sw);

    #pragma unroll
    for (int k0 = 0; k0 < K; k0 += 16) {
        uint32_t a[4];
        {
            int r  = mrow + (lane & 15);
            int cu = (k0 >> 3) + (lane >> 4);
            uint32_t addr = sx_base + (uint32_t)(r * K + ((cu ^ (r & 7)) * 8)) * 2u;
            ldsm_x4(a[0], a[1], a[2], a[3], addr);
        }
        #pragma unroll
        for (int nc = 0; nc < 8; nc++) {
            int k  = k0 + (lane & 15);
            int bu = nc * 2 + (lane >> 4);
            uint32_t addr = sw_base + (uint32_t)(k * 128 + ((bu ^ (k & 7)) * 8)) * 2u;
            uint32_t b0, b1, b2, b3;
            ldsm_x4_t(b0, b1, b2, b3, addr);
            mma16816(d[nc * 2],     a, b0, b1);
            mma16816(d[nc * 2 + 1], a, b2, b3);
        }
    }

    const int g   = lane >> 2;
    const int tig = lane & 3;
    const int ra  = row0 + mrow + g;
    const int rb  = ra + 8;
    #pragma unroll
    for (int jj = 0; jj < 16; jj++) {
        int c = jj * 8 + tig * 2;
        if (c < HID) {
            __half2 va = __floats2half2_rn(d[jj][0], d[jj][1]);
            __half2 vb = __floats2half2_rn(d[jj][2], d[jj][3]);
            if (ra < N_NODES) *reinterpret_cast<__half2*>(&yout[(size_t)ra * HID + c]) = va;
            if (rb < N_NODES) *reinterpret_cast<__half2*>(&yout[(size_t)rb * HID + c]) = vb;
        } else {
            int cz = c - HID;
            float bx = __ldg(&bias[cz]);
            float by = __ldg(&bias[cz + 1]);
            if (ra < N_NODES)
                *reinterpret_cast<float2*>(&zout[(size_t)ra * HID + cz]) =
                    make_float2(d[jj][0] + bx, d[jj][1] + by);
            if (rb < N_NODES)
                *reinterpret_cast<float2*>(&zout[(size_t)rb * HID + cz]) =
                    make_float2(d[jj][2] + bx, d[jj][3] + by);
        }
    }
}

constexpr int SMEM_TC1 = 2 * 128 * IN_DIM * (int)sizeof(__half);  // 64 KB
constexpr int SMEM_TC2 = 2 * 128 * HID * (int)sizeof(__half);     // 32 KB

// ---------------------------------------------------------------------------
// CSR gather: 8 threads per dst row; thread owns 8 fp16 message cols (16B
// load per neighbor). fp16 accumulation, 2 interleaved sets, and a software-
// pipelined index prefetch: the next int4 index quad loads while the current
// quad's features are accumulated (hides index L2 latency).
//   FINAL=false: g_h[dst] = half(h)       FINAL=true: out[dst] = h@Wc + bc
// ---------------------------------------------------------------------------
template <bool FINAL>
__global__ void __launch_bounds__(256) k_gather(
    const __half* __restrict__ ybuf,
    const float* __restrict__ zbuf,
    const float* __restrict__ Wc,
    const float* __restrict__ bc,
    float* __restrict__ out)
{
    int t = blockIdx.x * blockDim.x + threadIdx.x;
    int dst = t >> 3;
    int part = t & 7;
    if (dst >= N_NODES) return;
    uint32_t poff = (uint32_t)part << 4;   // byte offset of this 16B slice

    int deg = g_cnt[dst];
    int n = deg < STRIDE ? deg : STRIDE;
    const int* lst = &g_csr[(size_t)dst * STRIDE];

    __half2 zero2 = __float2half2_rn(0.f);
    __half2 aA[4] = {zero2, zero2, zero2, zero2};
    __half2 aB[4] = {zero2, zero2, zero2, zero2};

    int j = 0;
    if (n >= 4) {
        int4 cur = __ldg(reinterpret_cast<const int4*>(lst));
        // prefetch next quad while consuming current (reads within STRIDE
        // capacity are safe; prefetched garbage is only consumed when the
        // loop condition proves it valid)
        for (; j + 8 <= n; j += 4) {
            int4 nxt = __ldg(reinterpret_cast<const int4*>(lst + j + 4));
            accH(aA, cur.x, poff, ybuf);
            accH(aB, cur.y, poff, ybuf);
            accH(aA, cur.z, poff, ybuf);
            accH(aB, cur.w, poff, ybuf);
            cur = nxt;
        }
        accH(aA, cur.x, poff, ybuf);
        accH(aB, cur.y, poff, ybuf);
        accH(aA, cur.z, poff, ybuf);
        accH(aB, cur.w, poff, ybuf);
        j += 4;
    }
    for (; j < n; j++)
        accH(aA, __ldg(&lst[j]), poff, ybuf);

    // fp32 finish
    float2 s0 = __half22float2(aA[0]); float2 t0 = __half22float2(aB[0]);
    float2 s1 = __half22float2(aA[1]); float2 t1 = __half22float2(aB[1]);
    float2 s2 = __half22float2(aA[2]); float2 t2 = __half22float2(aB[2]);
    float2 s3 = __half22float2(aA[3]); float2 t3 = __half22float2(aB[3]);

    float inv = 1.0f / fmaxf((float)deg, 1.0f);
    size_t zb = (size_t)dst * HID + part * 8;
    float4 z0 = *reinterpret_cast<const float4*>(&zbuf[zb]);
    float4 z1 = *reinterpret_cast<const float4*>(&zbuf[zb + 4]);

    float h0 = fmaxf(fmaf(s0.x + t0.x, inv, z0.x), 0.f);
    float h1 = fmaxf(fmaf(s0.y + t0.y, inv, z0.y), 0.f);
    float h2 = fmaxf(fmaf(s1.x + t1.x, inv, z0.z), 0.f);
    float h3 = fmaxf(fmaf(s1.y + t1.y, inv, z0.w), 0.f);
    float h4 = fmaxf(fmaf(s2.x + t2.x, inv, z1.x), 0.f);
    float h5 = fmaxf(fmaf(s2.y + t2.y, inv, z1.y), 0.f);
    float h6 = fmaxf(fmaf(s3.x + t3.x, inv, z1.z), 0.f);
    float h7 = fmaxf(fmaf(s3.y + t3.y, inv, z1.w), 0.f);

    if (!FINAL) {
        __half2 hp[4];
        hp[0] = __floats2half2_rn(h0, h1);
        hp[1] = __floats2half2_rn(h2, h3);
        hp[2] = __floats2half2_rn(h4, h5);
        hp[3] = __floats2half2_rn(h6, h7);
        *reinterpret_cast<uint4*>(&g_h[(size_t)dst * HID + part * 8]) =
            *reinterpret_cast<uint4*>(hp);
    } else {
        float4 w0 = *reinterpret_cast<const float4*>(&Wc[part * 8]);
        float4 w1 = *reinterpret_cast<const float4*>(&Wc[part * 8 + 4]);
        float s = h0 * w0.x + h1 * w0.y + h2 * w0.z + h3 * w0.w
                + h4 * w1.x + h5 * w1.y + h6 * w1.z + h7 * w1.w;
        #pragma unroll
        for (int o = 4; o > 0; o >>= 1)
            s += __shfl_down_sync(0xffffffffu, s, o, 8);
        if (part == 0) out[dst] = s + __ldg(&bc[0]);
    }
}

// ---------------------------------------------------------------------------
extern "C" void kernel_launch(void* const* d_in, const int* in_sizes, int n_in,
                              void* d_out, int out_size)
{
    const float* x   = (const float*)d_in[0];
    const int*   ei  = (const int*)  d_in[1];
    const float* W1l = (const float*)d_in[2];
    const float* W1r = (const float*)d_in[3];
    const float* b1  = (const float*)d_in[4];
    const float* W2l = (const float*)d_in[5];
    const float* W2r = (const float*)d_in[6];
    const float* b2  = (const float*)d_in[7];
    const float* Wc  = (const float*)d_in[8];
    const float* bc  = (const float*)d_in[9];
    float* out = (float*)d_out;

    void *py = nullptr, *pz = nullptr, *ph = nullptr, *py2 = nullptr, *pz2 = nullptr;
    cudaGetSymbolAddress(&py,  g_y);
    cudaGetSymbolAddress(&pz,  g_z);
    cudaGetSymbolAddress(&ph,  g_h);
    cudaGetSymbolAddress(&py2, g_y2);
    cudaGetSymbolAddress(&pz2, g_z2);

    cudaFuncSetAttribute((const void*)&k_gemm_tc<IN_DIM, float>,
                         cudaFuncAttributeMaxDynamicSharedMemorySize, SMEM_TC1);
    cudaFuncSetAttribute((const void*)&k_gemm_tc<HID, __half>,
                         cudaFuncAttributeMaxDynamicSharedMemorySize, SMEM_TC2);

    constexpr int ZC_BLKS    = (N_NODES / 4 + 255) / 256;                 // 98
    constexpr int BUILD_BLKS = (E_EDGES / 4 + 255) / 256;                 // 1563
    constexpr int GEMM_BLKS  = (N_NODES + 127) / 128;                     // 782
    constexpr int GATH_BLKS  = (int)(((size_t)N_NODES * 8 + 255) / 256);  // 3125

    // Fork: [zero_cnt -> build] overlaps gemm1 (independent pipes).
    cudaStream_t s2;
    cudaEvent_t evFork, evJoin;
    cudaStreamCreateWithFlags(&s2, cudaStreamNonBlocking);
    cudaEventCreateWithFlags(&evFork, cudaEventDisableTiming);
    cudaEventCreateWithFlags(&evJoin, cudaEventDisableTiming);

    cudaEventRecord(evFork, 0);
    cudaStreamWaitEvent(s2, evFork, 0);
    k_zero_cnt<<<ZC_BLKS, 256, 0, s2>>>();
    k_build<<<BUILD_BLKS, 256, 0, s2>>>(ei);
    cudaEventRecord(evJoin, s2);

    k_gemm_tc<IN_DIM, float><<<GEMM_BLKS, 256, SMEM_TC1>>>(
        x, W1l, W1r, b1, (__half*)py, (float*)pz);

    cudaStreamWaitEvent(0, evJoin, 0);
    k_gather<false><<<GATH_BLKS, 256>>>((const __half*)py, (const float*)pz,
                                        nullptr, nullptr, nullptr);
    k_gemm_tc<HID, __half><<<GEMM_BLKS, 256, SMEM_TC2>>>(
        (const __half*)ph, W2l, W2r, b2, (__half*)py2, (float*)pz2);
    k_gather<true><<<GATH_BLKS, 256>>>((const __half*)py2, (const float*)pz2,
                                       Wc, bc, out);

    cudaEventDestroy(evFork);
    cudaEventDestroy(evJoin);
    cudaStreamDestroy(s2);
}